// round 10
// baseline (speedup 1.0000x reference)
#include <cuda_runtime.h>
#include <cuda_bf16.h>
#include <cstddef>

#define NN   50000
#define EE   800000
#define HDIM 128
#define GG   512
#define OUTD 64
#define BN_EPS 1e-5f

// ---------------- device scratch (no allocation allowed) ----------------
__device__ __align__(16) float g_bufX[NN * HDIM];            // layer output f32
__device__ __align__(16) float g_bufB[NN * HDIM];            // h1 pre-BN f32
__device__ __align__(16) __nv_bfloat16 g_Ahi[NN * HDIM];     // split A (hi)
__device__ __align__(16) __nv_bfloat16 g_Alo[NN * HDIM];     // split A (lo)
__device__ __align__(16) __nv_bfloat16 g_Wthi[7 * HDIM * HDIM]; // transposed W hi
__device__ __align__(16) __nv_bfloat16 g_Wtlo[7 * HDIM * HDIM]; // transposed W lo
__device__ __align__(16) float g_pool[GG * HDIM];
__device__ __align__(16) float g_head[GG * HDIM];
__device__ __align__(16) float g_stats[2 * HDIM];
__device__ __align__(16) float g_scaleK[HDIM];
__device__ __align__(16) float g_shiftK[HDIM];
// CSR scratch (deg zero at load; scan_kernel re-zeroes after use)
__device__ int g_deg[NN];
__device__ int g_rowptr[NN + 1];
__device__ int g_cursor[NN];
__device__ int g_csr[EE];

// ---------------- helpers ----------------
__device__ __forceinline__ void red_add_f4(float4* addr, float4 v) {
    asm volatile("red.global.add.v4.f32 [%0], {%1,%2,%3,%4};"
                 :: "l"(addr), "f"(v.x), "f"(v.y), "f"(v.z), "f"(v.w)
                 : "memory");
}

__device__ __forceinline__ void cp_async16(void* smem_dst, const void* gsrc) {
    unsigned d = (unsigned)__cvta_generic_to_shared(smem_dst);
    asm volatile("cp.async.cg.shared.global [%0], [%1], 16;"
                 :: "r"(d), "l"(gsrc));
}
#define CP_COMMIT()  asm volatile("cp.async.commit_group;")
#define CP_WAIT0()   asm volatile("cp.async.wait_group 0;")

// bf16 mma: D(16x8,f32) += A(16x16,bf16 row) * B(16x8,bf16 col)
__device__ __forceinline__ void mma_bf16(float* d, const unsigned* a,
                                         const unsigned* b) {
    asm volatile(
        "mma.sync.aligned.m16n8k16.row.col.f32.bf16.bf16.f32 "
        "{%0,%1,%2,%3}, {%4,%5,%6,%7}, {%8,%9}, {%0,%1,%2,%3};"
        : "+f"(d[0]), "+f"(d[1]), "+f"(d[2]), "+f"(d[3])
        : "r"(a[0]), "r"(a[1]), "r"(a[2]), "r"(a[3]), "r"(b[0]), "r"(b[1]));
}

__device__ __forceinline__ unsigned pack_bf16x2(__nv_bfloat16 a, __nv_bfloat16 b) {
    return ((unsigned)__bfloat16_as_ushort(b) << 16) |
           (unsigned)__bfloat16_as_ushort(a);
}

__device__ __forceinline__ void split_bf16(float v, __nv_bfloat16& hi,
                                           __nv_bfloat16& lo) {
    hi = __float2bfloat16_rn(v);
    lo = __float2bfloat16_rn(v - __bfloat162float(hi));
}

// float4 -> two uint2 (hi-packed, lo-packed)
__device__ __forceinline__ void split4(float4 v, uint2& hi, uint2& lo) {
    __nv_bfloat16 hx, lx, hy, ly, hz, lz, hw, lw;
    split_bf16(v.x, hx, lx); split_bf16(v.y, hy, ly);
    split_bf16(v.z, hz, lz); split_bf16(v.w, hw, lw);
    hi = make_uint2(pack_bf16x2(hx, hy), pack_bf16x2(hz, hw));
    lo = make_uint2(pack_bf16x2(lx, ly), pack_bf16x2(lz, lw));
}

// ---------------- CSR hist + weight prep (merged launch) ----------------
#define HIST_BLOCKS (EE / 256)   // 3125 exactly

__global__ void hist_prep_kernel(const int* __restrict__ dst,
                                 int* __restrict__ deg,
                                 const float* __restrict__ cW1,
                                 const float* __restrict__ cW2,
                                 const float* __restrict__ hW1,
                                 __nv_bfloat16* __restrict__ Wthi,
                                 __nv_bfloat16* __restrict__ Wtlo) {
    if (blockIdx.x < HIST_BLOCKS) {
        int e = blockIdx.x * 256 + threadIdx.x;
        atomicAdd(&deg[dst[e]], 1);
        return;
    }
    // weight prep: one block per matrix. src is [k][c] row-major;
    // output Wt[m][c][k] split into hi/lo.
    int m = blockIdx.x - HIST_BLOCKS;       // 0..6
    const float* src = (m < 3) ? (cW1 + m * 16384)
                     : (m < 6) ? (cW2 + (m - 3) * 16384)
                               : hW1;
    __nv_bfloat16* dhi = Wthi + m * 16384;
    __nv_bfloat16* dlo = Wtlo + m * 16384;
    for (int idx = threadIdx.x; idx < 16384; idx += 256) {
        int k = idx >> 7, c = idx & 127;
        __nv_bfloat16 h, l;
        split_bf16(src[idx], h, l);
        dhi[c * 128 + k] = h;
        dlo[c * 128 + k] = l;
    }
}

// single-block exclusive scan of deg -> rowptr+cursor; zeroes deg after use
__global__ void scan_kernel(int* __restrict__ deg,
                            int* __restrict__ rowptr,
                            int* __restrict__ cursor) {
    __shared__ int ssum[1024];
    const int T = 1024, CH = (NN + T - 1) / T;
    int t = threadIdx.x;
    int begin = t * CH;
    int end = begin + CH; if (end > NN) end = NN;
    int s = 0;
    for (int i = begin; i < end; i++) s += deg[i];
    ssum[t] = s;
    __syncthreads();
    for (int off = 1; off < T; off <<= 1) {
        int v = (t >= off) ? ssum[t - off] : 0;
        __syncthreads();
        ssum[t] += v;
        __syncthreads();
    }
    int run = (t == 0) ? 0 : ssum[t - 1];
    for (int i = begin; i < end; i++) {
        rowptr[i] = run;
        cursor[i] = run;
        run += deg[i];
        deg[i] = 0;
    }
    if (t == T - 1) rowptr[NN] = ssum[T - 1];
}

__global__ void fill_kernel(const int* __restrict__ src,
                            const int* __restrict__ dst,
                            int* __restrict__ cursor,
                            int* __restrict__ csr) {
    int e = blockIdx.x * blockDim.x + threadIdx.x;
    if (e >= EE) return;
    int pos = atomicAdd(&cursor[dst[e]], 1);
    csr[pos] = src[e];
}

// ---------------- aggregation: warp per node, writes split bf16 -----------
__global__ void gather_kernel(const float4* __restrict__ x,
                              uint2* __restrict__ aggHi,
                              uint2* __restrict__ aggLo,
                              const int* __restrict__ rowptr,
                              const int* __restrict__ csr,
                              float* __restrict__ stats) {
    if (blockIdx.x == 0 && threadIdx.x < 2 * HDIM) stats[threadIdx.x] = 0.f;
    int n = blockIdx.x * 8 + (threadIdx.x >> 5);
    if (n >= NN) return;
    int lane = threadIdx.x & 31;
    int b = rowptr[n], e = rowptr[n + 1];
    float4 a0 = x[(size_t)n * 32 + lane];
    float4 a1 = make_float4(0.f, 0.f, 0.f, 0.f);
    float4 a2 = make_float4(0.f, 0.f, 0.f, 0.f);
    float4 a3 = make_float4(0.f, 0.f, 0.f, 0.f);
    int i = b;
    for (; i + 8 <= e; i += 8) {
        int s0 = csr[i],     s1 = csr[i + 1], s2 = csr[i + 2], s3 = csr[i + 3];
        int s4 = csr[i + 4], s5 = csr[i + 5], s6 = csr[i + 6], s7 = csr[i + 7];
        float4 v0 = x[(size_t)s0 * 32 + lane];
        float4 v1 = x[(size_t)s1 * 32 + lane];
        float4 v2 = x[(size_t)s2 * 32 + lane];
        float4 v3 = x[(size_t)s3 * 32 + lane];
        float4 v4 = x[(size_t)s4 * 32 + lane];
        float4 v5 = x[(size_t)s5 * 32 + lane];
        float4 v6 = x[(size_t)s6 * 32 + lane];
        float4 v7 = x[(size_t)s7 * 32 + lane];
        a0.x += v0.x; a0.y += v0.y; a0.z += v0.z; a0.w += v0.w;
        a1.x += v1.x; a1.y += v1.y; a1.z += v1.z; a1.w += v1.w;
        a2.x += v2.x; a2.y += v2.y; a2.z += v2.z; a2.w += v2.w;
        a3.x += v3.x; a3.y += v3.y; a3.z += v3.z; a3.w += v3.w;
        a0.x += v4.x; a0.y += v4.y; a0.z += v4.z; a0.w += v4.w;
        a1.x += v5.x; a1.y += v5.y; a1.z += v5.z; a1.w += v5.w;
        a2.x += v6.x; a2.y += v6.y; a2.z += v6.z; a2.w += v6.w;
        a3.x += v7.x; a3.y += v7.y; a3.z += v7.z; a3.w += v7.w;
    }
    for (; i + 4 <= e; i += 4) {
        int s0 = csr[i], s1 = csr[i + 1], s2 = csr[i + 2], s3 = csr[i + 3];
        float4 v0 = x[(size_t)s0 * 32 + lane];
        float4 v1 = x[(size_t)s1 * 32 + lane];
        float4 v2 = x[(size_t)s2 * 32 + lane];
        float4 v3 = x[(size_t)s3 * 32 + lane];
        a0.x += v0.x; a0.y += v0.y; a0.z += v0.z; a0.w += v0.w;
        a1.x += v1.x; a1.y += v1.y; a1.z += v1.z; a1.w += v1.w;
        a2.x += v2.x; a2.y += v2.y; a2.z += v2.z; a2.w += v2.w;
        a3.x += v3.x; a3.y += v3.y; a3.z += v3.z; a3.w += v3.w;
    }
    for (; i < e; i++) {
        float4 v = x[(size_t)csr[i] * 32 + lane];
        a0.x += v.x; a0.y += v.y; a0.z += v.z; a0.w += v.w;
    }
    a0.x += a1.x + a2.x + a3.x;
    a0.y += a1.y + a2.y + a3.y;
    a0.z += a1.z + a2.z + a3.z;
    a0.w += a1.w + a2.w + a3.w;
    uint2 hi, lo;
    split4(a0, hi, lo);
    aggHi[(size_t)n * 32 + lane] = hi;
    aggLo[(size_t)n * 32 + lane] = lo;
}

// ---------------- convert: f32 buffer -> split bf16 (opt BN+ReLU) ---------
template <bool BN>
__global__ void convert_kernel(const float4* __restrict__ in,
                               const float* __restrict__ scaleK,
                               const float* __restrict__ shiftK,
                               uint2* __restrict__ hi, uint2* __restrict__ lo,
                               int total4) {
    int i = blockIdx.x * blockDim.x + threadIdx.x;
    if (i >= total4) return;
    float4 v = in[i];
    if (BN) {
        int k = (i & 31) * 4;
        float4 sc = *(const float4*)(scaleK + k);
        float4 sh = *(const float4*)(shiftK + k);
        v.x = fmaxf(fmaf(v.x, sc.x, sh.x), 0.f);
        v.y = fmaxf(fmaf(v.y, sc.y, sh.y), 0.f);
        v.z = fmaxf(fmaf(v.z, sc.z, sh.z), 0.f);
        v.w = fmaxf(fmaf(v.w, sc.w, sh.w), 0.f);
    }
    uint2 h, l;
    split4(v, h, l);
    hi[i] = h;
    lo[i] = l;
}

// ---------------- GEMM on pre-split bf16: no transform phases -------------
// A (hi,lo): bf16 [M][128]; Wt (hi,lo): bf16 [128 cols][128 k].
// smem (elems; bf16): sAhi[2][128][40], sAlo, sWhi, sWlo  (pad 40 -> 80B rows,
// fragment LDS verified conflict-free). K-chunk 32, 4 chunks, double-buffered.
#define GEMMB_SMEM_BYTES 81920
#define ABUF 5120                 // 128*40 elems per buffer

template <bool POST_RELU, bool STATS>
__global__ void __launch_bounds__(256, 2)
gemm_bf16(const __nv_bfloat16* __restrict__ Ahi,
          const __nv_bfloat16* __restrict__ Alo,
          const __nv_bfloat16* __restrict__ Wthi,
          const __nv_bfloat16* __restrict__ Wtlo,
          const float* __restrict__ bias, float* __restrict__ out,
          float* __restrict__ stats, int M) {
    extern __shared__ char smem[];
    __nv_bfloat16* sAhi = (__nv_bfloat16*)smem;          // [2][ABUF]
    __nv_bfloat16* sAlo = sAhi + 2 * ABUF;
    __nv_bfloat16* sWhi = sAlo + 2 * ABUF;
    __nv_bfloat16* sWlo = sWhi + 2 * ABUF;

    const int tid  = threadIdx.x;
    const int w    = tid >> 5;
    const int lane = tid & 31;
    const int grp  = lane >> 2;
    const int q    = lane & 3;
    const int mBase = (w & 3) * 32;
    const int nBase = (w >> 2) * 64;
    const int base_row = blockIdx.x * 128;

    float acc[2][8][4];
#pragma unroll
    for (int mt = 0; mt < 2; mt++)
#pragma unroll
        for (int nt = 0; nt < 8; nt++)
#pragma unroll
            for (int c = 0; c < 4; c++) acc[mt][nt][c] = 0.f;

    auto issue_tile = [&](int buf, int kb) {
#pragma unroll
        for (int t = 0; t < 2; t++) {
            int idx = tid + t * 256;           // 512 chunks per array
            int row = idx >> 2, j = idx & 3;   // j: 16B (=8 bf16) chunk
            int gr  = base_row + row;
            int cgr = gr < M ? gr : 0;
            int so = buf * ABUF + row * 40 + j * 8;
            cp_async16(sAhi + so, Ahi + (size_t)cgr * 128 + kb + j * 8);
            cp_async16(sAlo + so, Alo + (size_t)cgr * 128 + kb + j * 8);
            cp_async16(sWhi + so, Wthi + (size_t)row * 128 + kb + j * 8);
            cp_async16(sWlo + so, Wtlo + (size_t)row * 128 + kb + j * 8);
        }
        CP_COMMIT();
    };

    issue_tile(0, 0);

    for (int kb4 = 0; kb4 < 4; kb4++) {
        const int buf = kb4 & 1;
        CP_WAIT0();
        __syncthreads();                   // tile visible; prev reads done
        if (kb4 < 3) issue_tile(buf ^ 1, (kb4 + 1) * 32);

#pragma unroll
        for (int ks = 0; ks < 2; ks++) {
            const int ko = ks * 16;
            unsigned ah[2][4], al[2][4];
#pragma unroll
            for (int mt = 0; mt < 2; mt++) {
                int r = mBase + mt * 16 + grp;
                int b0 = buf * ABUF + r * 40 + ko + 2 * q;
                ah[mt][0] = *(const unsigned*)(sAhi + b0);
                ah[mt][1] = *(const unsigned*)(sAhi + b0 + 8 * 40);
                ah[mt][2] = *(const unsigned*)(sAhi + b0 + 8);
                ah[mt][3] = *(const unsigned*)(sAhi + b0 + 8 * 40 + 8);
                al[mt][0] = *(const unsigned*)(sAlo + b0);
                al[mt][1] = *(const unsigned*)(sAlo + b0 + 8 * 40);
                al[mt][2] = *(const unsigned*)(sAlo + b0 + 8);
                al[mt][3] = *(const unsigned*)(sAlo + b0 + 8 * 40 + 8);
            }
#pragma unroll
            for (int nt = 0; nt < 8; nt++) {
                int n = nBase + nt * 8 + grp;
                int wb = buf * ABUF + n * 40 + ko + 2 * q;
                unsigned bh[2], bl[2];
                bh[0] = *(const unsigned*)(sWhi + wb);
                bh[1] = *(const unsigned*)(sWhi + wb + 8);
                bl[0] = *(const unsigned*)(sWlo + wb);
                bl[1] = *(const unsigned*)(sWlo + wb + 8);
#pragma unroll
                for (int mt = 0; mt < 2; mt++) {
                    mma_bf16(acc[mt][nt], ah[mt], bh);
                    mma_bf16(acc[mt][nt], ah[mt], bl);
                    mma_bf16(acc[mt][nt], al[mt], bh);
                }
            }
        }
    }

    // ---- epilogue ----
    float csum[8][2], csq[8][2];
    if (STATS) {
#pragma unroll
        for (int nt = 0; nt < 8; nt++) {
            csum[nt][0] = csum[nt][1] = 0.f;
            csq[nt][0]  = csq[nt][1]  = 0.f;
        }
    }
#pragma unroll
    for (int nt = 0; nt < 8; nt++) {
        int col0 = nBase + nt * 8 + 2 * q;
        float b0 = bias[col0], b1 = bias[col0 + 1];
#pragma unroll
        for (int mt = 0; mt < 2; mt++) {
#pragma unroll
            for (int half = 0; half < 2; half++) {
                int r = base_row + mBase + mt * 16 + grp + half * 8;
                if (r < M) {
                    float v0 = acc[mt][nt][2 * half + 0] + b0;
                    float v1 = acc[mt][nt][2 * half + 1] + b1;
                    if (POST_RELU) { v0 = fmaxf(v0, 0.f); v1 = fmaxf(v1, 0.f); }
                    *(float2*)(out + (size_t)r * 128 + col0) =
                        make_float2(v0, v1);
                    if (STATS) {
                        csum[nt][0] += v0;      csum[nt][1] += v1;
                        csq[nt][0]  += v0 * v0; csq[nt][1]  += v1 * v1;
                    }
                }
            }
        }
    }

    if (STATS) {
        __syncthreads();
        float* ssum = (float*)sAhi;          // 1KB scratch
        float* ssq  = ssum + 128;
        ssum[tid] = 0.f;                     // 256 threads zero both arrays
        __syncthreads();
#pragma unroll
        for (int nt = 0; nt < 8; nt++) {
            int col0 = nBase + nt * 8 + 2 * q;
            atomicAdd(&ssum[col0],     csum[nt][0]);
            atomicAdd(&ssum[col0 + 1], csum[nt][1]);
            atomicAdd(&ssq[col0],      csq[nt][0]);
            atomicAdd(&ssq[col0 + 1],  csq[nt][1]);
        }
        __syncthreads();
        if (tid < 128) {
            atomicAdd(&stats[tid],       ssum[tid]);
            atomicAdd(&stats[128 + tid], ssq[tid]);
        }
    }
}

__global__ void bn_finalize_kernel(const float* __restrict__ stats,
                                   const float* __restrict__ gamma,
                                   const float* __restrict__ beta,
                                   float* __restrict__ scaleK,
                                   float* __restrict__ shiftK, float invM) {
    int c = threadIdx.x;
    float mu   = stats[c] * invM;
    float var  = stats[128 + c] * invM - mu * mu;
    float rstd = rsqrtf(var + BN_EPS);
    float sc   = gamma[c] * rstd;
    scaleK[c] = sc;
    shiftK[c] = beta[c] - mu * sc;
}

__global__ void zero_pool_kernel(float4* __restrict__ pool) {
    int i = blockIdx.x * blockDim.x + threadIdx.x;
    pool[i] = make_float4(0.f, 0.f, 0.f, 0.f);
}

__global__ void pool_scatter_kernel(const float4* __restrict__ x,
                                    float4* __restrict__ pool,
                                    const int* __restrict__ batch,
                                    int N) {
    int n = blockIdx.x * 8 + (threadIdx.x >> 5);
    if (n >= N) return;
    int lane = threadIdx.x & 31;
    int g = batch[n];
    float4 v = x[(size_t)n * 32 + lane];
    red_add_f4(&pool[(size_t)g * 32 + lane], v);
}

__global__ void head2_kernel(const float* __restrict__ Hh,
                             const float* __restrict__ W,
                             const float* __restrict__ b,
                             float* __restrict__ out) {
    __shared__ float row[128];
    int g = blockIdx.x;
    int c = threadIdx.x;
    row[c]      = Hh[(size_t)g * 128 + c];
    row[c + 64] = Hh[(size_t)g * 128 + 64 + c];
    __syncthreads();
    float acc = b[c];
#pragma unroll 8
    for (int k = 0; k < 128; k++) acc = fmaf(row[k], W[k * 64 + c], acc);
    out[(size_t)g * 64 + c] = acc;
}

// ---------------- launcher ----------------
extern "C" void kernel_launch(void* const* d_in, const int* in_sizes, int n_in,
                              void* d_out, int out_size) {
    const float* x    = (const float*)d_in[0];
    const float* cW1  = (const float*)d_in[1];
    const float* cb1  = (const float*)d_in[2];
    const float* cgam = (const float*)d_in[3];
    const float* cbet = (const float*)d_in[4];
    const float* cW2  = (const float*)d_in[5];
    const float* cb2  = (const float*)d_in[6];
    const float* hW1  = (const float*)d_in[7];
    const float* hb1  = (const float*)d_in[8];
    const float* hW2  = (const float*)d_in[9];
    const float* hb2  = (const float*)d_in[10];
    const int* ei    = (const int*)d_in[11];   // [2, E] int32
    const int* batch = (const int*)d_in[12];   // [N]    int32
    float* out = (float*)d_out;

    float *bufX, *bufB, *pool, *head, *stats, *scaleK, *shiftK;
    __nv_bfloat16 *Ahi, *Alo, *Wthi, *Wtlo;
    int *deg, *rowptr, *cursor, *csr;
    cudaGetSymbolAddress((void**)&bufX,   g_bufX);
    cudaGetSymbolAddress((void**)&bufB,   g_bufB);
    cudaGetSymbolAddress((void**)&Ahi,    g_Ahi);
    cudaGetSymbolAddress((void**)&Alo,    g_Alo);
    cudaGetSymbolAddress((void**)&Wthi,   g_Wthi);
    cudaGetSymbolAddress((void**)&Wtlo,   g_Wtlo);
    cudaGetSymbolAddress((void**)&pool,   g_pool);
    cudaGetSymbolAddress((void**)&head,   g_head);
    cudaGetSymbolAddress((void**)&stats,  g_stats);
    cudaGetSymbolAddress((void**)&scaleK, g_scaleK);
    cudaGetSymbolAddress((void**)&shiftK, g_shiftK);
    cudaGetSymbolAddress((void**)&deg,    g_deg);
    cudaGetSymbolAddress((void**)&rowptr, g_rowptr);
    cudaGetSymbolAddress((void**)&cursor, g_cursor);
    cudaGetSymbolAddress((void**)&csr,    g_csr);

    cudaFuncSetAttribute(gemm_bf16<false, true>,
                         cudaFuncAttributeMaxDynamicSharedMemorySize,
                         GEMMB_SMEM_BYTES);
    cudaFuncSetAttribute(gemm_bf16<true, false>,
                         cudaFuncAttributeMaxDynamicSharedMemorySize,
                         GEMMB_SMEM_BYTES);

    const int* e_src = ei;
    const int* e_dst = ei + EE;
    const int gemm_blocks = (NN + 127) / 128;  // 391
    const int conv_blocks = (NN * 32 + 255) / 256;

    // CSR build + weight prep; launch index 3 = first gather (profiler slot)
    hist_prep_kernel<<<HIST_BLOCKS + 7, 256>>>(e_dst, deg, cW1, cW2, hW1,
                                               Wthi, Wtlo);
    scan_kernel<<<1, 1024>>>(deg, rowptr, cursor);
    fill_kernel<<<(EE + 255) / 256, 256>>>(e_src, e_dst, cursor, csr);

    for (int l = 0; l < 3; l++) {
        const float* in = (l == 0) ? x : bufX;
        gather_kernel<<<(NN + 7) / 8, 256>>>(
            (const float4*)in, (uint2*)Ahi, (uint2*)Alo, rowptr, csr, stats);
        gemm_bf16<false, true><<<gemm_blocks, 256, GEMMB_SMEM_BYTES>>>(
            Ahi, Alo, Wthi + l * 16384, Wtlo + l * 16384,
            cb1 + l * HDIM, bufB, stats, NN);
        bn_finalize_kernel<<<1, 128>>>(stats, cgam + l * HDIM, cbet + l * HDIM,
                                       scaleK, shiftK, 1.0f / NN);
        convert_kernel<true><<<conv_blocks, 256>>>(
            (const float4*)bufB, scaleK, shiftK,
            (uint2*)Ahi, (uint2*)Alo, NN * 32);
        gemm_bf16<true, false><<<gemm_blocks, 256, GEMMB_SMEM_BYTES>>>(
            Ahi, Alo, Wthi + (3 + l) * 16384, Wtlo + (3 + l) * 16384,
            cb2 + l * HDIM, bufX, nullptr, NN);
    }

    zero_pool_kernel<<<64, 256>>>((float4*)pool);
    pool_scatter_kernel<<<(NN + 7) / 8, 256>>>(
        (const float4*)bufX, (float4*)pool, batch, NN);
    convert_kernel<false><<<(GG * 32 + 255) / 256, 256>>>(
        (const float4*)pool, nullptr, nullptr,
        (uint2*)Ahi, (uint2*)Alo, GG * 32);
    gemm_bf16<true, false><<<(GG + 127) / 128, 256, GEMMB_SMEM_BYTES>>>(
        Ahi, Alo, Wthi + 6 * 16384, Wtlo + 6 * 16384, hb1, head, nullptr, GG);
    head2_kernel<<<GG, 64>>>(head, hW2, hb2, out);
}